// round 16
// baseline (speedup 1.0000x reference)
#include <cuda_runtime.h>
#include <cstdint>

#define BS 32
#define LA 300
#define LB 1024
#define H  512
#define NROW (H*H)

// ---------------- scratch ----------------
__device__ float g_part[BS*16*H];
__device__ float g_bm[BS*H];               // b_mean [b][e]
__device__ uint2 g_bfrag[8192];            // fragment-ordered tf32 B blob (64KB)
__device__ float g_T[(long)BS*NROW];       // [b][k*H+d], pre-rounded tf32

// ---------------- helpers ----------------
__device__ __forceinline__ uint32_t f2tf(float f) {
    uint32_t r;
    asm("cvt.rna.tf32.f32 %0, %1;" : "=r"(r) : "f"(f));
    return r;
}
__device__ __forceinline__ void mma_tf32(float* c, uint32_t a0, uint32_t a1,
                                         uint32_t a2, uint32_t a3,
                                         uint32_t b0, uint32_t b1) {
    asm volatile("mma.sync.aligned.m16n8k8.row.col.f32.tf32.tf32.f32 "
                 "{%0,%1,%2,%3}, {%4,%5,%6,%7}, {%8,%9}, {%0,%1,%2,%3};"
                 : "+f"(c[0]), "+f"(c[1]), "+f"(c[2]), "+f"(c[3])
                 : "r"(a0), "r"(a1), "r"(a2), "r"(a3), "r"(b0), "r"(b1));
}

// ---------------- kernel 1: b_mean (coalesced) ----------------
__global__ void k_bmean_part(const float* __restrict__ feat_b) {
    int chunk = blockIdx.x, b = blockIdx.y, t = threadIdx.x;
    const float4* p = (const float4*)(feat_b + ((long)b*LB + (long)chunk*64)*H) + t;
    float4 s = make_float4(0.f,0.f,0.f,0.f);
    #pragma unroll 8
    for (int j = 0; j < 64; j++) {
        float4 v = __ldg(p + (long)j*128);
        s.x += v.x; s.y += v.y; s.z += v.z; s.w += v.w;
    }
    *((float4*)(g_part + ((long)b*16 + chunk)*H) + t) = s;
}
__global__ void k_bmean_red() {
    long idx = (long)blockIdx.x*512 + threadIdx.x;
    long b = idx >> 9, d = idx & 511;
    float s = 0.f;
    #pragma unroll
    for (int c = 0; c < 16; c++) s += g_part[(b*16 + c)*H + d];
    g_bm[idx] = s * (1.0f/1024.0f);
}

// ---------------- kernel 1b: B fragment blob ----------------
__global__ void k_bfrag() {
    int idx = blockIdx.x*256 + threadIdx.x;     // 8192
    int lane = idx & 31;
    int nt = (idx >> 5) & 3;
    int cm = idx >> 7;                          // c*2+m
    int c = cm >> 1, m = cm & 1;
    int n = nt*8 + (lane >> 2);
    int k = c*16 + (lane & 3)*4 + m*2;
    uint2 v;
    v.x = f2tf(g_bm[n*H + k]);
    v.y = f2tf(g_bm[n*H + k + 1]);
    g_bfrag[idx] = v;
}

// ---------------- kernel 2: T[b][r] = W2d x bm^T via mma.sync tf32 ----------------
// [R15-proven] CTA 256 thr / 8 warps, 128 rows, 6-stage cp.async, blob B.
// Launched in 4 quarters of 512 CTAs (bid_off) to enable overlap with gemm2.
#define SDW 132
#define WM_SMEM (65536 + 6*8192)    // 114688

__global__ void __launch_bounds__(256, 2) k_wgemm_mma(const float* __restrict__ Wg,
                                                      int bid_off) {
    extern __shared__ char smem[];
    uint2* sbf = (uint2*)smem;                 // [8192] B frags
    char* sStg = smem + 65536;                 // 6 stages x 8KB
    float* sD = (float*)smem;                  // epilogue aliases blob

    int tid = threadIdx.x;
    int wid = tid >> 5, lane = tid & 31;
    int group = lane >> 2, tg = lane & 3;
    long r0 = (long)(blockIdx.x + bid_off) * 128;
    int m0 = wid * 16;

    // group 0: B blob (contiguous 64KB)
    {
        const char* src = (const char*)g_bfrag;
        uint32_t sb0 = (uint32_t)__cvta_generic_to_shared(smem);
        #pragma unroll
        for (int p = 0; p < 16; p++) {
            int i = p*256 + tid;
            asm volatile("cp.async.cg.shared.global [%0], [%1], 16;"
                         :: "r"(sb0 + i*16), "l"(src + (long)i*16));
        }
        asm volatile("cp.async.commit_group;" ::: "memory");
    }

    auto issue = [&](int c, int stg) {
        uint32_t st = (uint32_t)__cvta_generic_to_shared(sStg) + stg*8192;
        #pragma unroll
        for (int q = 0; q < 2; q++) {
            int g = q*256 + tid;
            int row = g >> 2, i = g & 3;
            const float* src = Wg + (r0 + row)*H + c*16 + i*4;
            asm volatile("cp.async.cg.shared.global [%0], [%1], 16;"
                         :: "r"(st + row*64 + i*16), "l"(src));
        }
        asm volatile("cp.async.commit_group;" ::: "memory");
    };
    issue(0,0); issue(1,1); issue(2,2); issue(3,3); issue(4,4);

    float acc[4][4];
    #pragma unroll
    for (int i = 0; i < 4; i++)
        #pragma unroll
        for (int j = 0; j < 4; j++) acc[i][j] = 0.f;

    int rstg = 0, wstg = 5;
    for (int c = 0; c < 32; c++) {
        if (c < 28)       asm volatile("cp.async.wait_group 4;" ::: "memory");
        else if (c == 28) asm volatile("cp.async.wait_group 3;" ::: "memory");
        else if (c == 29) asm volatile("cp.async.wait_group 2;" ::: "memory");
        else if (c == 30) asm volatile("cp.async.wait_group 1;" ::: "memory");
        else              asm volatile("cp.async.wait_group 0;" ::: "memory");
        __syncthreads();
        if (c + 5 < 32) {
            issue(c + 5, wstg);
            if (++wstg == 6) wstg = 0;
        }

        const uint32_t* sA = (const uint32_t*)(sStg + rstg*8192);
        if (++rstg == 6) rstg = 0;
        uint4 a0v = *(const uint4*)(sA + (m0 + group)*16 + tg*4);
        uint4 a1v = *(const uint4*)(sA + (m0 + group + 8)*16 + tg*4);
        uint32_t ax0 = f2tf(__uint_as_float(a0v.x)), ax1 = f2tf(__uint_as_float(a1v.x));
        uint32_t ay0 = f2tf(__uint_as_float(a0v.y)), ay1 = f2tf(__uint_as_float(a1v.y));
        uint32_t az0 = f2tf(__uint_as_float(a0v.z)), az1 = f2tf(__uint_as_float(a1v.z));
        uint32_t aw0 = f2tf(__uint_as_float(a0v.w)), aw1 = f2tf(__uint_as_float(a1v.w));

        const uint2* bb = sbf + c*8*32 + lane;
        #pragma unroll
        for (int nt = 0; nt < 4; nt++) {
            uint2 b0 = bb[nt*32];           // m=0
            uint2 b1 = bb[(4 + nt)*32];     // m=1
            mma_tf32(acc[nt], ax0, ax1, ay0, ay1, b0.x, b0.y);
            mma_tf32(acc[nt], az0, az1, aw0, aw1, b1.x, b1.y);
        }
    }

    __syncthreads();   // all warps done reading blob before aliasing as sD
    #pragma unroll
    for (int nt = 0; nt < 4; nt++) {
        int n0 = nt*8 + tg*2;
        int rl = m0 + group;
        sD[(n0  )*SDW + rl    ] = acc[nt][0];
        sD[(n0+1)*SDW + rl    ] = acc[nt][1];
        sD[(n0  )*SDW + rl + 8] = acc[nt][2];
        sD[(n0+1)*SDW + rl + 8] = acc[nt][3];
    }
    __syncthreads();
    #pragma unroll
    for (int p = 0; p < 16; p++) {
        int i = p*256 + tid;
        int n = i >> 7, rl = i & 127;
        uint32_t t = f2tf(sD[n*SDW + rl]);     // pre-round for gemm2 B
        g_T[(long)n*NROW + r0 + rl] = __uint_as_float(t);
    }
}

// ---------------- kernel 3: fused = feat_a @ T^T (+bias +feat_a) via mma ----------
// [R15-proven] tile 64x128, kt passed as param (one slice per wgemm quarter).
#define G2_STG   12288
#define G2_SMEM  (4*G2_STG)

__global__ void __launch_bounds__(256) k_gemm2(const float* __restrict__ Araw,
                                               const float* __restrict__ bias,
                                               float* __restrict__ out, int kt) {
    extern __shared__ char smem[];
    int b = blockIdx.z, mt = blockIdx.x;
    int tid = threadIdx.x;
    int wid = tid >> 5, lane = tid & 31;
    int group = lane >> 2, tg = lane & 3;
    int wm = wid & 3, wc = wid >> 2;
    int row0 = mt * 64;
    const float* Ab = Araw + (long)b*LA*H;
    const float* Bb = g_T + (long)b*NROW + (long)kt*128*H;

    auto issue = [&](int c) {
        char* st = smem + (c & 3)*G2_STG;
        {
            int row = tid >> 2, i = tid & 3;
            const float* src = Ab + (long)(row0 + row)*H + c*16 + i*4;
            unsigned dst = (unsigned)__cvta_generic_to_shared(st + row*64 + i*16);
            int vsz = (row0 + row < LA) ? 16 : 0;
            asm volatile("cp.async.cg.shared.global [%0], [%1], 16, %2;"
                         :: "r"(dst), "l"(src), "r"(vsz));
        }
        #pragma unroll
        for (int q = 0; q < 2; q++) {
            int g2 = q*256 + tid;
            int row = g2 >> 2, i = g2 & 3;
            const float* src = Bb + (long)row*H + c*16 + i*4;
            unsigned dst = (unsigned)__cvta_generic_to_shared(st + 4096 + row*64 + i*16);
            asm volatile("cp.async.cg.shared.global [%0], [%1], 16;"
                         :: "r"(dst), "l"(src));
        }
        asm volatile("cp.async.commit_group;" ::: "memory");
    };

    issue(0); issue(1); issue(2);

    float acc[8][4];
    #pragma unroll
    for (int i = 0; i < 8; i++)
        #pragma unroll
        for (int j = 0; j < 4; j++) acc[i][j] = 0.f;

    for (int c = 0; c < 32; c++) {
        if (c < 30)       asm volatile("cp.async.wait_group 2;" ::: "memory");
        else if (c == 30) asm volatile("cp.async.wait_group 1;" ::: "memory");
        else              asm volatile("cp.async.wait_group 0;" ::: "memory");
        __syncthreads();
        if (c + 3 < 32) issue(c + 3);

        const char* st = smem + (c & 3)*G2_STG;
        const uint32_t* sA = (const uint32_t*)st;
        const uint32_t* sBt = (const uint32_t*)(st + 4096);

        uint4 a0v = *(const uint4*)(sA + (wm*16 + group)*16 + tg*4);
        uint4 a1v = *(const uint4*)(sA + (wm*16 + group + 8)*16 + tg*4);
        uint32_t ax0 = f2tf(__uint_as_float(a0v.x)), ax1 = f2tf(__uint_as_float(a1v.x));
        uint32_t ay0 = f2tf(__uint_as_float(a0v.y)), ay1 = f2tf(__uint_as_float(a1v.y));
        uint32_t az0 = f2tf(__uint_as_float(a0v.z)), az1 = f2tf(__uint_as_float(a1v.z));
        uint32_t aw0 = f2tf(__uint_as_float(a0v.w)), aw1 = f2tf(__uint_as_float(a1v.w));
        #pragma unroll
        for (int nt = 0; nt < 8; nt++) {
            uint4 bv = *(const uint4*)(sBt + (wc*64 + nt*8 + group)*16 + tg*4);
            mma_tf32(acc[nt], ax0, ax1, ay0, ay1, bv.x, bv.y);
            mma_tf32(acc[nt], az0, az1, aw0, aw1, bv.z, bv.w);
        }
    }

    int grow = row0 + wm*16 + group;
    #pragma unroll
    for (int nt = 0; nt < 8; nt++) {
        int col = kt*128 + wc*64 + nt*8 + tg*2;
        float2 bb = *(const float2*)(bias + col);
        #pragma unroll
        for (int h = 0; h < 2; h++) {
            int r = grow + h*8;
            if (r < LA) {
                float2 fa = *(const float2*)(Ab + (long)r*H + col);
                float2 o;
                o.x = acc[nt][h*2+0] + bb.x + fa.x;
                o.y = acc[nt][h*2+1] + bb.y + fa.y;
                *(float2*)(out + ((long)b*LA + r)*H + col) = o;
            }
        }
    }
}

// ---------------- kernel 4: LayerNorm, warp-per-row ----------------
__global__ void k_ln(const float* __restrict__ gamma, const float* __restrict__ beta,
                     float* __restrict__ out) {
    int wid = threadIdx.x >> 5, lane = threadIdx.x & 31;
    long row = (long)blockIdx.x*8 + wid;
    float4* xr = reinterpret_cast<float4*>(out + row*H);
    const float4* g4 = reinterpret_cast<const float4*>(gamma);
    const float4* b4 = reinterpret_cast<const float4*>(beta);

    float4 v[4];
    float s = 0.f, sq = 0.f;
    #pragma unroll
    for (int i = 0; i < 4; i++) {
        v[i] = xr[lane + i*32];
        s  += v[i].x + v[i].y + v[i].z + v[i].w;
        sq += v[i].x*v[i].x + v[i].y*v[i].y + v[i].z*v[i].z + v[i].w*v[i].w;
    }
    #pragma unroll
    for (int o = 16; o > 0; o >>= 1) {
        s  += __shfl_xor_sync(0xffffffffu, s,  o);
        sq += __shfl_xor_sync(0xffffffffu, sq, o);
    }
    float mu = s * (1.0f/H);
    float var = sq * (1.0f/H) - mu*mu;
    float rstd = rsqrtf(var + 1e-5f);
    #pragma unroll
    for (int i = 0; i < 4; i++) {
        float4 gg = __ldg(g4 + lane + i*32);
        float4 be = __ldg(b4 + lane + i*32);
        float4 o;
        o.x = (v[i].x - mu)*rstd*gg.x + be.x;
        o.y = (v[i].y - mu)*rstd*gg.y + be.y;
        o.z = (v[i].z - mu)*rstd*gg.z + be.z;
        o.w = (v[i].w - mu)*rstd*gg.w + be.w;
        xr[lane + i*32] = o;
    }
}

// ---------------- launch: fork-join overlap of wgemm quarters with gemm2 slices ----
extern "C" void kernel_launch(void* const* d_in, const int* in_sizes, int n_in,
                              void* d_out, int out_size) {
    const float* feat_a = (const float*)d_in[0];
    const float* feat_b = (const float*)d_in[1];
    const float* W      = (const float*)d_in[2];
    const float* bias   = (const float*)d_in[3];
    const float* gamma  = (const float*)d_in[4];
    const float* beta   = (const float*)d_in[5];
    float* out = (float*)d_out;

    static cudaStream_t s2 = nullptr;
    static cudaEvent_t eq[4], efin;
    if (!s2) {   // first call is the uncaptured correctness run
        cudaFuncSetAttribute(k_wgemm_mma, cudaFuncAttributeMaxDynamicSharedMemorySize, WM_SMEM);
        cudaFuncSetAttribute(k_gemm2, cudaFuncAttributeMaxDynamicSharedMemorySize, G2_SMEM);
        cudaStreamCreateWithFlags(&s2, cudaStreamNonBlocking);
        for (int i = 0; i < 4; i++) cudaEventCreateWithFlags(&eq[i], cudaEventDisableTiming);
        cudaEventCreateWithFlags(&efin, cudaEventDisableTiming);
    }

    k_bmean_part<<<dim3(16,32), 128>>>(feat_b);
    k_bmean_red<<<32, 512>>>();
    k_bfrag<<<32, 256>>>();

    for (int q = 0; q < 4; q++) {
        k_wgemm_mma<<<512, 256, WM_SMEM>>>(W, q*512);
        cudaEventRecord(eq[q], 0);
        cudaStreamWaitEvent(s2, eq[q], 0);
        k_gemm2<<<dim3(5,1,32), 256, G2_SMEM, s2>>>(feat_a, bias, out, q);
    }
    k_ln<<<1200, 256, 0, s2>>>(gamma, beta, out);
    cudaEventRecord(efin, s2);
    cudaStreamWaitEvent(0, efin, 0);
}

// round 17
// speedup vs baseline: 1.2465x; 1.2465x over previous
#include <cuda_runtime.h>
#include <cstdint>

#define BS 32
#define LA 300
#define LB 1024
#define H  512
#define NROW (H*H)

// ---------------- scratch ----------------
__device__ float g_part[BS*16*H];
__device__ uint2 g_bfrag[8192];            // fragment-ordered tf32 B blob (64KB)
__device__ float g_T[(long)BS*NROW];       // [b][k*H+d], pre-rounded tf32

// ---------------- helpers ----------------
__device__ __forceinline__ uint32_t f2tf(float f) {
    uint32_t r;
    asm("cvt.rna.tf32.f32 %0, %1;" : "=r"(r) : "f"(f));
    return r;
}
__device__ __forceinline__ void mma_tf32(float* c, uint32_t a0, uint32_t a1,
                                         uint32_t a2, uint32_t a3,
                                         uint32_t b0, uint32_t b1) {
    asm volatile("mma.sync.aligned.m16n8k8.row.col.f32.tf32.tf32.f32 "
                 "{%0,%1,%2,%3}, {%4,%5,%6,%7}, {%8,%9}, {%0,%1,%2,%3};"
                 : "+f"(c[0]), "+f"(c[1]), "+f"(c[2]), "+f"(c[3])
                 : "r"(a0), "r"(a1), "r"(a2), "r"(a3), "r"(b0), "r"(b1));
}

// ---------------- kernel 1: b_mean partials (coalesced) ----------------
__global__ void k_bmean_part(const float* __restrict__ feat_b) {
    int chunk = blockIdx.x, b = blockIdx.y, t = threadIdx.x;
    const float4* p = (const float4*)(feat_b + ((long)b*LB + (long)chunk*64)*H) + t;
    float4 s = make_float4(0.f,0.f,0.f,0.f);
    #pragma unroll 8
    for (int j = 0; j < 64; j++) {
        float4 v = __ldg(p + (long)j*128);
        s.x += v.x; s.y += v.y; s.z += v.z; s.w += v.w;
    }
    *((float4*)(g_part + ((long)b*16 + chunk)*H) + t) = s;
}

// ---------------- kernel 1b: reduce partials + emit tf32 fragment blob ----------
// grid 32 (b = n), 512 thr (d = k). Thread (n,k) computes mean, then even-k lanes
// pair with k+1 via shfl and write blob entry at the R12-proven fragment address:
// idx = ((c*2+m)*4 + nt)*32 + lane,  nt=n>>3, lane=(n&7)*4+((k>>2)&3), c=k>>4, m=(k>>1)&1.
__global__ void k_bmean_red_bfrag() {
    int n = blockIdx.x, k = threadIdx.x;
    float s = 0.f;
    #pragma unroll
    for (int c = 0; c < 16; c++) s += g_part[((long)n*16 + c)*H + k];
    float mean = s * (1.0f/1024.0f);
    uint32_t t = f2tf(mean);
    uint32_t t1 = __shfl_down_sync(0xffffffffu, t, 1);
    if ((k & 1) == 0) {
        int c  = k >> 4;
        int m  = (k >> 1) & 1;
        int nt = n >> 3;
        int lane = (n & 7)*4 + ((k >> 2) & 3);
        uint2 v; v.x = t; v.y = t1;
        g_bfrag[((c*2 + m)*4 + nt)*32 + lane] = v;
    }
}

// ---------------- kernel 2: T[b][r] = W2d x bm^T via mma.sync tf32 ----------------
// [R15-proven] CTA 256 thr / 8 warps, 128 rows, 6-stage cp.async, blob B, 2 CTA/SM.
#define SDW 132
#define WM_SMEM (65536 + 6*8192)    // 114688

__global__ void __launch_bounds__(256, 2) k_wgemm_mma(const float* __restrict__ Wg) {
    extern __shared__ char smem[];
    uint2* sbf = (uint2*)smem;                 // [8192] B frags
    char* sStg = smem + 65536;                 // 6 stages x 8KB
    float* sD = (float*)smem;                  // epilogue aliases blob

    int tid = threadIdx.x;
    int wid = tid >> 5, lane = tid & 31;
    int group = lane >> 2, tg = lane & 3;
    long r0 = (long)blockIdx.x * 128;
    int m0 = wid * 16;

    // group 0: B blob (contiguous 64KB)
    {
        const char* src = (const char*)g_bfrag;
        uint32_t sb0 = (uint32_t)__cvta_generic_to_shared(smem);
        #pragma unroll
        for (int p = 0; p < 16; p++) {
            int i = p*256 + tid;
            asm volatile("cp.async.cg.shared.global [%0], [%1], 16;"
                         :: "r"(sb0 + i*16), "l"(src + (long)i*16));
        }
        asm volatile("cp.async.commit_group;" ::: "memory");
    }

    auto issue = [&](int c, int stg) {
        uint32_t st = (uint32_t)__cvta_generic_to_shared(sStg) + stg*8192;
        #pragma unroll
        for (int q = 0; q < 2; q++) {
            int g = q*256 + tid;
            int row = g >> 2, i = g & 3;
            const float* src = Wg + (r0 + row)*H + c*16 + i*4;
            asm volatile("cp.async.cg.shared.global [%0], [%1], 16;"
                         :: "r"(st + row*64 + i*16), "l"(src));
        }
        asm volatile("cp.async.commit_group;" ::: "memory");
    };
    issue(0,0); issue(1,1); issue(2,2); issue(3,3); issue(4,4);

    float acc[4][4];
    #pragma unroll
    for (int i = 0; i < 4; i++)
        #pragma unroll
        for (int j = 0; j < 4; j++) acc[i][j] = 0.f;

    int rstg = 0, wstg = 5;
    for (int c = 0; c < 32; c++) {
        if (c < 28)       asm volatile("cp.async.wait_group 4;" ::: "memory");
        else if (c == 28) asm volatile("cp.async.wait_group 3;" ::: "memory");
        else if (c == 29) asm volatile("cp.async.wait_group 2;" ::: "memory");
        else if (c == 30) asm volatile("cp.async.wait_group 1;" ::: "memory");
        else              asm volatile("cp.async.wait_group 0;" ::: "memory");
        __syncthreads();
        if (c + 5 < 32) {
            issue(c + 5, wstg);
            if (++wstg == 6) wstg = 0;
        }

        const uint32_t* sA = (const uint32_t*)(sStg + rstg*8192);
        if (++rstg == 6) rstg = 0;
        uint4 a0v = *(const uint4*)(sA + (m0 + group)*16 + tg*4);
        uint4 a1v = *(const uint4*)(sA + (m0 + group + 8)*16 + tg*4);
        uint32_t ax0 = f2tf(__uint_as_float(a0v.x)), ax1 = f2tf(__uint_as_float(a1v.x));
        uint32_t ay0 = f2tf(__uint_as_float(a0v.y)), ay1 = f2tf(__uint_as_float(a1v.y));
        uint32_t az0 = f2tf(__uint_as_float(a0v.z)), az1 = f2tf(__uint_as_float(a1v.z));
        uint32_t aw0 = f2tf(__uint_as_float(a0v.w)), aw1 = f2tf(__uint_as_float(a1v.w));

        const uint2* bb = sbf + c*8*32 + lane;
        #pragma unroll
        for (int nt = 0; nt < 4; nt++) {
            uint2 b0 = bb[nt*32];           // m=0
            uint2 b1 = bb[(4 + nt)*32];     // m=1
            mma_tf32(acc[nt], ax0, ax1, ay0, ay1, b0.x, b0.y);
            mma_tf32(acc[nt], az0, az1, aw0, aw1, b1.x, b1.y);
        }
    }

    __syncthreads();   // all warps done reading blob before aliasing as sD
    #pragma unroll
    for (int nt = 0; nt < 4; nt++) {
        int n0 = nt*8 + tg*2;
        int rl = m0 + group;
        sD[(n0  )*SDW + rl    ] = acc[nt][0];
        sD[(n0+1)*SDW + rl    ] = acc[nt][1];
        sD[(n0  )*SDW + rl + 8] = acc[nt][2];
        sD[(n0+1)*SDW + rl + 8] = acc[nt][3];
    }
    __syncthreads();
    #pragma unroll
    for (int p = 0; p < 16; p++) {
        int i = p*256 + tid;
        int n = i >> 7, rl = i & 127;
        uint32_t t = f2tf(sD[n*SDW + rl]);     // pre-round for gemm2 B
        g_T[(long)n*NROW + r0 + rl] = __uint_as_float(t);
    }
}

// ---------------- kernel 3: fused = feat_a @ T^T (+bias +feat_a) via mma ----------
// [R15-proven] tile 64x128, 8 warps, 4-stage cp.async, correct tail waits.
#define G2_STG   12288
#define G2_SMEM  (4*G2_STG)

__global__ void __launch_bounds__(256) k_gemm2(const float* __restrict__ Araw,
                                               const float* __restrict__ bias,
                                               float* __restrict__ out) {
    extern __shared__ char smem[];
    int b = blockIdx.z, kt = blockIdx.y, mt = blockIdx.x;
    int tid = threadIdx.x;
    int wid = tid >> 5, lane = tid & 31;
    int group = lane >> 2, tg = lane & 3;
    int wm = wid & 3, wc = wid >> 2;
    int row0 = mt * 64;
    const float* Ab = Araw + (long)b*LA*H;
    const float* Bb = g_T + (long)b*NROW + (long)kt*128*H;

    auto issue = [&](int c) {
        char* st = smem + (c & 3)*G2_STG;
        {
            int row = tid >> 2, i = tid & 3;
            const float* src = Ab + (long)(row0 + row)*H + c*16 + i*4;
            unsigned dst = (unsigned)__cvta_generic_to_shared(st + row*64 + i*16);
            int vsz = (row0 + row < LA) ? 16 : 0;
            asm volatile("cp.async.cg.shared.global [%0], [%1], 16, %2;"
                         :: "r"(dst), "l"(src), "r"(vsz));
        }
        #pragma unroll
        for (int q = 0; q < 2; q++) {
            int g2 = q*256 + tid;
            int row = g2 >> 2, i = g2 & 3;
            const float* src = Bb + (long)row*H + c*16 + i*4;
            unsigned dst = (unsigned)__cvta_generic_to_shared(st + 4096 + row*64 + i*16);
            asm volatile("cp.async.cg.shared.global [%0], [%1], 16;"
                         :: "r"(dst), "l"(src));
        }
        asm volatile("cp.async.commit_group;" ::: "memory");
    };

    issue(0); issue(1); issue(2);

    float acc[8][4];
    #pragma unroll
    for (int i = 0; i < 8; i++)
        #pragma unroll
        for (int j = 0; j < 4; j++) acc[i][j] = 0.f;

    for (int c = 0; c < 32; c++) {
        if (c < 30)       asm volatile("cp.async.wait_group 2;" ::: "memory");
        else if (c == 30) asm volatile("cp.async.wait_group 1;" ::: "memory");
        else              asm volatile("cp.async.wait_group 0;" ::: "memory");
        __syncthreads();
        if (c + 3 < 32) issue(c + 3);

        const char* st = smem + (c & 3)*G2_STG;
        const uint32_t* sA = (const uint32_t*)st;
        const uint32_t* sBt = (const uint32_t*)(st + 4096);

        uint4 a0v = *(const uint4*)(sA + (wm*16 + group)*16 + tg*4);
        uint4 a1v = *(const uint4*)(sA + (wm*16 + group + 8)*16 + tg*4);
        uint32_t ax0 = f2tf(__uint_as_float(a0v.x)), ax1 = f2tf(__uint_as_float(a1v.x));
        uint32_t ay0 = f2tf(__uint_as_float(a0v.y)), ay1 = f2tf(__uint_as_float(a1v.y));
        uint32_t az0 = f2tf(__uint_as_float(a0v.z)), az1 = f2tf(__uint_as_float(a1v.z));
        uint32_t aw0 = f2tf(__uint_as_float(a0v.w)), aw1 = f2tf(__uint_as_float(a1v.w));
        #pragma unroll
        for (int nt = 0; nt < 8; nt++) {
            uint4 bv = *(const uint4*)(sBt + (wc*64 + nt*8 + group)*16 + tg*4);
            mma_tf32(acc[nt], ax0, ax1, ay0, ay1, bv.x, bv.y);
            mma_tf32(acc[nt], az0, az1, aw0, aw1, bv.z, bv.w);
        }
    }

    int grow = row0 + wm*16 + group;
    #pragma unroll
    for (int nt = 0; nt < 8; nt++) {
        int col = kt*128 + wc*64 + nt*8 + tg*2;
        float2 bb = *(const float2*)(bias + col);
        #pragma unroll
        for (int h = 0; h < 2; h++) {
            int r = grow + h*8;
            if (r < LA) {
                float2 fa = *(const float2*)(Ab + (long)r*H + col);
                float2 o;
                o.x = acc[nt][h*2+0] + bb.x + fa.x;
                o.y = acc[nt][h*2+1] + bb.y + fa.y;
                *(float2*)(out + ((long)b*LA + r)*H + col) = o;
            }
        }
    }
}

// ---------------- kernel 4: LayerNorm, warp-per-row ----------------
__global__ void k_ln(const float* __restrict__ gamma, const float* __restrict__ beta,
                     float* __restrict__ out) {
    int wid = threadIdx.x >> 5, lane = threadIdx.x & 31;
    long row = (long)blockIdx.x*8 + wid;
    float4* xr = reinterpret_cast<float4*>(out + row*H);
    const float4* g4 = reinterpret_cast<const float4*>(gamma);
    const float4* b4 = reinterpret_cast<const float4*>(beta);

    float4 v[4];
    float s = 0.f, sq = 0.f;
    #pragma unroll
    for (int i = 0; i < 4; i++) {
        v[i] = xr[lane + i*32];
        s  += v[i].x + v[i].y + v[i].z + v[i].w;
        sq += v[i].x*v[i].x + v[i].y*v[i].y + v[i].z*v[i].z + v[i].w*v[i].w;
    }
    #pragma unroll
    for (int o = 16; o > 0; o >>= 1) {
        s  += __shfl_xor_sync(0xffffffffu, s,  o);
        sq += __shfl_xor_sync(0xffffffffu, sq, o);
    }
    float mu = s * (1.0f/H);
    float var = sq * (1.0f/H) - mu*mu;
    float rstd = rsqrtf(var + 1e-5f);
    #pragma unroll
    for (int i = 0; i < 4; i++) {
        float4 gg = __ldg(g4 + lane + i*32);
        float4 be = __ldg(b4 + lane + i*32);
        float4 o;
        o.x = (v[i].x - mu)*rstd*gg.x + be.x;
        o.y = (v[i].y - mu)*rstd*gg.y + be.y;
        o.z = (v[i].z - mu)*rstd*gg.z + be.z;
        o.w = (v[i].w - mu)*rstd*gg.w + be.w;
        xr[lane + i*32] = o;
    }
}

// ---------------- launch ----------------
extern "C" void kernel_launch(void* const* d_in, const int* in_sizes, int n_in,
                              void* d_out, int out_size) {
    const float* feat_a = (const float*)d_in[0];
    const float* feat_b = (const float*)d_in[1];
    const float* W      = (const float*)d_in[2];
    const float* bias   = (const float*)d_in[3];
    const float* gamma  = (const float*)d_in[4];
    const float* beta   = (const float*)d_in[5];
    float* out = (float*)d_out;

    static bool attr_done = false;
    if (!attr_done) {
        cudaFuncSetAttribute(k_wgemm_mma, cudaFuncAttributeMaxDynamicSharedMemorySize, WM_SMEM);
        cudaFuncSetAttribute(k_gemm2, cudaFuncAttributeMaxDynamicSharedMemorySize, G2_SMEM);
        attr_done = true;
    }

    k_bmean_part<<<dim3(16,32), 128>>>(feat_b);
    k_bmean_red_bfrag<<<32, 512>>>();
    k_wgemm_mma<<<2048, 256, WM_SMEM>>>(W);
    k_gemm2<<<dim3(5,4,32), 256, G2_SMEM>>>(feat_a, bias, out);
    k_ln<<<1200, 256>>>(gamma, beta, out);
}